// round 12
// baseline (speedup 1.0000x reference)
#include <cuda_runtime.h>
#include <cuda_fp16.h>
#include <math.h>
#include <stdint.h>

#define B_DIM 2048
#define D_DIM 512
#define C_DIM 32000
#define SCALE_F 32.0f
#define MARGIN_F 16.0f

// ---------------- scratch (device globals; no allocation allowed) ----------
__device__ int g_tgt[B_DIM];
__device__ __align__(16) __half g_xh[(size_t)B_DIM * D_DIM];   // normalized fp16 X
__device__ __align__(16) __half g_wh[(size_t)C_DIM * D_DIM];   // normalized fp16 W

// ---------------- helpers ----------------------------------------------------
static __device__ __forceinline__ uint32_t smem_u32(const void* p) {
    uint32_t a;
    asm("{ .reg .u64 t; cvta.to.shared.u64 t, %1; cvt.u32.u64 %0, t; }" : "=r"(a) : "l"(p));
    return a;
}
static __device__ __forceinline__ void cp16(uint32_t dst, const void* src) {
    asm volatile("cp.async.cg.shared.global [%0], [%1], 16;" :: "r"(dst), "l"(src) : "memory");
}
static __device__ __forceinline__ void ldsm_x4(uint32_t* r, uint32_t addr) {
    asm volatile("ldmatrix.sync.aligned.m8n8.x4.shared.b16 {%0,%1,%2,%3}, [%4];"
                 : "=r"(r[0]), "=r"(r[1]), "=r"(r[2]), "=r"(r[3]) : "r"(addr));
}
static __device__ __forceinline__ void mma_f16(float* d, const uint32_t* a,
                                               uint32_t b0, uint32_t b1) {
    asm volatile(
        "mma.sync.aligned.m16n8k16.row.col.f32.f16.f16.f32 "
        "{%0,%1,%2,%3}, {%4,%5,%6,%7}, {%8,%9}, {%0,%1,%2,%3};"
        : "+f"(d[0]), "+f"(d[1]), "+f"(d[2]), "+f"(d[3])
        : "r"(a[0]), "r"(a[1]), "r"(a[2]), "r"(a[3]), "r"(b0), "r"(b1));
}
static __device__ __forceinline__ uint32_t swz(uint32_t row, uint32_t quad) {
    return row * 128u + ((quad ^ (row & 7u)) << 4);
}

// ---------------- prep: L2-normalize row, emit fp16 --------------------------
__global__ void prep_h(const float* __restrict__ src, __half* __restrict__ dst) {
    int row = blockIdx.x;
    size_t base = (size_t)row * D_DIM + threadIdx.x * 4;
    float4 v = *reinterpret_cast<const float4*>(src + base);
    float f[4] = {v.x, v.y, v.z, v.w};

    float ss = f[0]*f[0] + f[1]*f[1] + f[2]*f[2] + f[3]*f[3];
    #pragma unroll
    for (int o = 16; o > 0; o >>= 1) ss += __shfl_xor_sync(0xffffffffu, ss, o);
    __shared__ float ws_[4], s_inv;
    int lane = threadIdx.x & 31, w = threadIdx.x >> 5;
    if (lane == 0) ws_[w] = ss;
    __syncthreads();
    if (threadIdx.x == 0)
        s_inv = 1.0f / fmaxf(sqrtf(ws_[0] + ws_[1] + ws_[2] + ws_[3]), 1e-12f);
    __syncthreads();
    float inv = s_inv;

    __half h[4];
    #pragma unroll
    for (int i = 0; i < 4; i++) h[i] = __float2half_rn(f[i] * inv);
    uint32_t lo = (uint32_t)*(uint16_t*)&h[0] | ((uint32_t)*(uint16_t*)&h[1] << 16);
    uint32_t hi = (uint32_t)*(uint16_t*)&h[2] | ((uint32_t)*(uint16_t*)&h[3] << 16);
    *reinterpret_cast<uint2*>(dst + base) = make_uint2(lo, hi);
}

// ---------------- decode targets (proven global probe) ----------------------
__global__ void decode_targets(const void* __restrict__ targets,
                               int* __restrict__ tgt) {
    const int tid = threadIdx.x;  // one block, 1024 threads
    const int* ti = reinterpret_cast<const int*>(targets);
    int odd = ti[2 * tid + 1];
    int any_nonzero = __syncthreads_or(odd != 0);
    const bool is64 = (any_nonzero == 0);
    #pragma unroll
    for (int r = 0; r < 2; r++) {
        int b = tid + r * 1024;
        int t;
        if (is64) t = (int)reinterpret_cast<const long long*>(targets)[b];
        else      t = ti[b];
        tgt[b] = t;
    }
}

// ---------------- GEMM: fp16 mma.sync, single product -----------------------
// CTA tile 128(m) x 256(n), BK = 64 halves. 256 threads, 8 warps (2m x 4n),
// warp tile m64 x n64. 4-stage cp.async pipeline, 48KB/stage, early issue.
// smem: [0..512) targets, [1024 + s*49152): stage s = A 16K | B 32K
#define STAGE_H 49152u
#define SMEM_H (1024u + 4u * STAGE_H)

__global__ void __launch_bounds__(256, 1)
gemm_kernel(float* __restrict__ out_loss, float* __restrict__ out_pred) {
    extern __shared__ __align__(128) unsigned char smem[];
    const uint32_t sb = smem_u32(smem);
    const uint32_t st0 = sb + 1024u;
    const int tid = threadIdx.x;
    const int wid = tid >> 5, lane = tid & 31;
    const int wm = wid & 1, wn = wid >> 1;    // 2m x 4n warp grid

    const int bid = blockIdx.x;          // m-fastest: consecutive CTAs share W panel
    const int mt = bid & 15, nt = bid >> 4;
    const int m0 = mt * 128, n0 = nt * 256;

    int* s_tg = reinterpret_cast<int*>(smem);
    if (tid < 128) s_tg[tid] = g_tgt[m0 + tid] - n0;
    __syncthreads();

    // ---- g2s issue of one K-chunk (64 halves = 128B rows) into stage s ----
    auto issue = [&](int s, int chunk) {
        uint32_t st = st0 + (uint32_t)s * STAGE_H;
        int k0 = chunk * 64;
        #pragma unroll
        for (int i = 0; i < 4; i++) {          // A: 1024 cp16
            int idx = tid + i * 256;
            uint32_t row = (uint32_t)idx >> 3, q = (uint32_t)idx & 7;
            cp16(st + swz(row, q), g_xh + ((size_t)(m0 + row) * D_DIM + k0 + q * 8));
        }
        #pragma unroll
        for (int i = 0; i < 8; i++) {          // B: 2048 cp16
            int idx = tid + i * 256;
            uint32_t row = (uint32_t)idx >> 3, q = (uint32_t)idx & 7;
            cp16(st + 16384u + swz(row, q), g_wh + ((size_t)(n0 + row) * D_DIM + k0 + q * 8));
        }
        asm volatile("cp.async.commit_group;" ::: "memory");
    };

    float acc[4][8][4];
    #pragma unroll
    for (int i = 0; i < 4; i++)
        #pragma unroll
        for (int j = 0; j < 8; j++)
            #pragma unroll
            for (int q = 0; q < 4; q++) acc[i][j][q] = 0.0f;

    issue(0, 0); issue(1, 1); issue(2, 2);

    const uint32_t arow = lane & 15;      // ldmatrix row within 16
    const uint32_t akq  = lane >> 4;      // k-quad select (0/1)

    #pragma unroll 1
    for (int c = 0; c < 8; c++) {
        if      (c <= 5) asm volatile("cp.async.wait_group 2;" ::: "memory");
        else if (c == 6) asm volatile("cp.async.wait_group 1;" ::: "memory");
        else             asm volatile("cp.async.wait_group 0;" ::: "memory");
        __syncthreads();
        // Early issue: stage (c+3)&3 was computed at iteration c-1 -> free now.
        if (c + 3 < 8) issue((c + 3) & 3, c + 3);

        uint32_t st = st0 + (uint32_t)(c & 3) * STAGE_H;
        #pragma unroll
        for (int s = 0; s < 4; s++) {     // 4 k16 steps
            uint32_t qb = 2 * s + akq;
            uint32_t ah[4][4];
            #pragma unroll
            for (int mi = 0; mi < 4; mi++)
                ldsm_x4(ah[mi], st + swz((uint32_t)(wm * 64 + mi * 16) + arow, qb));
            // B in two halves to cap live registers
            #pragma unroll
            for (int half = 0; half < 2; half++) {
                uint32_t bh[2][4];
                #pragma unroll
                for (int nj = 0; nj < 2; nj++)
                    ldsm_x4(bh[nj], st + 16384u +
                            swz((uint32_t)(wn * 64 + (half * 2 + nj) * 16) + arow, qb));
                #pragma unroll
                for (int mi = 0; mi < 4; mi++)
                    #pragma unroll
                    for (int j = 0; j < 4; j++) {
                        int nb = half * 4 + j;
                        int nj = j >> 1, sel = j & 1;
                        mma_f16(acc[mi][nb], ah[mi], bh[nj][0 + sel], bh[nj][2 + sel]);
                    }
            }
        }
    }

    // ---- epilogue: v = acc*32 (rows pre-normalized); fused margin ----------
    const int gr = lane >> 2, gc = lane & 3;
    #pragma unroll
    for (int mi = 0; mi < 4; mi++) {
        int rl = wm * 64 + mi * 16 + gr;      // local rows rl, rl+8
        int t0 = s_tg[rl], t1 = s_tg[rl + 8];
        size_t off0 = (size_t)(m0 + rl) * C_DIM + n0;
        size_t off1 = off0 + (size_t)8 * C_DIM;
        #pragma unroll
        for (int nb = 0; nb < 8; nb++) {
            int col = wn * 64 + nb * 8 + gc * 2;
            float2 v0 = make_float2(acc[mi][nb][0] * SCALE_F, acc[mi][nb][1] * SCALE_F);
            float2 v1 = make_float2(acc[mi][nb][2] * SCALE_F, acc[mi][nb][3] * SCALE_F);
            *reinterpret_cast<float2*>(out_pred + off0 + col) = v0;
            *reinterpret_cast<float2*>(out_pred + off1 + col) = v1;
            float2 u0 = v0, u1 = v1;
            if (t0 == col)     u0.x -= MARGIN_F;
            if (t0 == col + 1) u0.y -= MARGIN_F;
            if (t1 == col)     u1.x -= MARGIN_F;
            if (t1 == col + 1) u1.y -= MARGIN_F;
            *reinterpret_cast<float2*>(out_loss + off0 + col) = u0;
            *reinterpret_cast<float2*>(out_loss + off1 + col) = u1;
        }
    }
}

// ---------------------------------------------------------------------------
extern "C" void kernel_launch(void* const* d_in, const int* in_sizes, int n_in,
                              void* d_out, int out_size) {
    const float* x  = (const float*)d_in[0];
    const float* w  = (const float*)d_in[1];
    const void*  tg = d_in[2];

    float* out_loss = (float*)d_out;
    float* out_pred = out_loss + (size_t)B_DIM * C_DIM;

    int* tgt;
    __half *xh, *wh;
    cudaGetSymbolAddress((void**)&tgt, g_tgt);
    cudaGetSymbolAddress((void**)&xh, g_xh);
    cudaGetSymbolAddress((void**)&wh, g_wh);

    decode_targets<<<1, 1024>>>(tg, tgt);
    prep_h<<<B_DIM, 128>>>(x, xh);
    prep_h<<<C_DIM, 128>>>(w, wh);

    cudaFuncSetAttribute(gemm_kernel, cudaFuncAttributeMaxDynamicSharedMemorySize, SMEM_H);
    gemm_kernel<<<2000, 256, SMEM_H>>>(out_loss, out_pred);
}